// round 9
// baseline (speedup 1.0000x reference)
#include <cuda_runtime.h>
#include <cstdint>

// SigmaModel, persistent-CTA, 1024 threads, crossbar-balanced thread tile 4r x 9c.
// h = relu([s,a] @ W1^T + b1); tri = h @ W2^T + b2;
// out[b,i,j] = tri[t(min(i,j),max(i,j))], diag -> exp.

#define BATCH    131072
#define SDIM     32
#define ADIM     8
#define INDIM    40
#define HID      64
#define TRI      528
#define ROWS     64               // rows per tile
#define NT       1024
#define GRID     152              // GB300 SM count
#define NTILES   (BATCH / ROWS)   // 2048
#define NPAD     580              // W2 k-major stride (mult of 4)
#define TPAD     578              // tri chunk stride
#define HPAD     66               // H stride: even (float2 loads), mod32=2 (banked rows)
#define XPAD     40               // X stride (16B-aligned cp.async rows)

// shared memory layout (float offsets)
#define SM_W2    0                // [64][NPAD] = 37120, persists
#define SM_TRI   37120            // [16][TPAD] = 9248 (epilogue chunk)
#define SM_H     46368            // [64][HPAD] = 4224
#define SM_X     50592            // [64][XPAD] = 2560
#define SM_W1    53152            // [40][64] transposed = 2560
#define SM_B1    55712            // [64]
#define SM_B2    55776            // [576]
#define SM_TBL   56352            // int[1024]
#define SM_FLOATS 57376           // 229504 bytes

typedef unsigned long long u64;

__device__ __forceinline__ u64 pack2(float lo, float hi) {
    u64 r; asm("mov.b64 %0, {%1, %2};" : "=l"(r) : "f"(lo), "f"(hi)); return r;
}
__device__ __forceinline__ void unpack2(u64 v, float& lo, float& hi) {
    asm("mov.b64 {%0, %1}, %2;" : "=f"(lo), "=f"(hi) : "l"(v));
}
__device__ __forceinline__ void fma2(u64& d, u64 a, u64 b) {
    asm("fma.rn.f32x2 %0, %1, %2, %0;" : "+l"(d) : "l"(a), "l"(b));
}
__device__ __forceinline__ uint32_t smem_u32(const void* p) {
    uint32_t r;
    asm("{ .reg .u64 t; cvta.to.shared.u64 t, %1; cvt.u32.u64 %0, t; }" : "=r"(r) : "l"(p));
    return r;
}
__device__ __forceinline__ void cp16(uint32_t dst, const void* src) {
    asm volatile("cp.async.ca.shared.global [%0], [%1], 16;" :: "r"(dst), "l"(src));
}
__device__ __forceinline__ void cp_commit() {
    asm volatile("cp.async.commit_group;" ::: "memory");
}
__device__ __forceinline__ void cp_wait0() {
    asm volatile("cp.async.wait_group 0;" ::: "memory");
}

__global__ void __launch_bounds__(NT, 1)
sigma_persist_kernel(const float* __restrict__ s,
                     const float* __restrict__ a,
                     const float* __restrict__ W1,
                     const float* __restrict__ b1,
                     const float* __restrict__ W2,
                     const float* __restrict__ b2,
                     float* __restrict__ out) {
    extern __shared__ float smem[];
    float* sW2  = smem + SM_W2;
    float* sTri = smem + SM_TRI;
    float* sH   = smem + SM_H;
    float* sX   = smem + SM_X;
    float* sW1  = smem + SM_W1;
    float* sB1  = smem + SM_B1;
    float* sB2  = smem + SM_B2;
    int*   sTbl = (int*)(smem + SM_TBL);

    const int tid = threadIdx.x;
    const uint32_t sXaddr = smem_u32(sX);

    // ================= one-time staging =================
    // W2[t][k] -> sW2[k][t] via LDG.128 along k
    for (int idx = tid; idx < TRI * (HID / 4); idx += NT) {
        int t = idx >> 4, k4 = idx & 15;
        float4 w = *reinterpret_cast<const float4*>(&W2[t * HID + k4 * 4]);
        sW2[(4 * k4 + 0) * NPAD + t] = w.x;
        sW2[(4 * k4 + 1) * NPAD + t] = w.y;
        sW2[(4 * k4 + 2) * NPAD + t] = w.z;
        sW2[(4 * k4 + 3) * NPAD + t] = w.w;
    }
    // zero-pad W2 cols [TRI, NPAD)
    for (int idx = tid; idx < HID * (NPAD - TRI); idx += NT) {
        int k = idx / (NPAD - TRI), t = TRI + (idx - k * (NPAD - TRI));
        sW2[k * NPAD + t] = 0.0f;
    }
    // W1[hh][k] -> sW1[k][hh]
    for (int idx = tid; idx < HID * INDIM; idx += NT) {
        int hh = idx / INDIM, k = idx - hh * INDIM;
        sW1[k * HID + hh] = W1[idx];
    }
    if (tid < HID) sB1[tid] = b1[tid];
    for (int idx = tid; idx < 576; idx += NT)
        sB2[idx] = (idx < TRI) ? b2[idx] : 0.0f;
    // scatter table: out (i,j) -> tri index | diag flag
    for (int o = tid; o < 1024; o += NT) {
        int i = o >> 5, j = o & 31;
        int ii = (i < j) ? i : j;
        int jj = (i < j) ? j : i;
        int t = ii * 32 - ((ii * (ii + 1)) >> 1) + jj;
        sTbl[o] = t | ((i == j) ? (1 << 16) : 0);
    }

    // prefetch X for first tile
    const int tile0 = blockIdx.x;
    {
        int row0 = tile0 * ROWS;
        if (tid < 512) {
            int r = tid >> 3, c4 = tid & 7;
            cp16(sXaddr + (r * XPAD + c4 * 4) * 4, &s[(size_t)(row0 + r) * SDIM + c4 * 4]);
        } else if (tid < 640) {
            int t2 = tid - 512, r2 = t2 >> 1, d4 = t2 & 1;
            cp16(sXaddr + (r2 * XPAD + SDIM + d4 * 4) * 4,
                 &a[(size_t)(row0 + r2) * ADIM + d4 * 4]);
        }
        cp_commit();
    }
    cp_wait0();
    __syncthreads();

    // GEMM mapping: 32 warps = 2 row-blocks(32r) x 16 col-blocks(36c).
    // Lane: rg = lane&7 (rows rg + 8m, m<4), cg = lane>>3 (9 cols).
    const int wi   = tid >> 5, lane = tid & 31;
    const int rb   = wi >> 4,  cb   = wi & 15;
    const int rg   = lane & 7, cg   = lane >> 3;
    const int wcol = cb * 36;
    const int4* tbl4 = reinterpret_cast<const int4*>(sTbl);

    // ================= persistent tile loop =================
    for (int tile = tile0; tile < NTILES; tile += GRID) {
        const int row0 = tile * ROWS;

        // ---- Phase 1: H = relu(X @ W1^T + b1) ----
        {
            const int r  = tid >> 4;           // 0..63
            const int hg = (tid & 15) * 4;     // 4 hidden cols = 2 pairs
            u64 acc[2];
            acc[0] = *reinterpret_cast<const u64*>(&sB1[hg]);
            acc[1] = *reinterpret_cast<const u64*>(&sB1[hg + 2]);
            const float* xrow = &sX[r * XPAD];
#pragma unroll 5
            for (int k = 0; k < INDIM; ++k) {
                u64 xb = pack2(xrow[k], xrow[k]);
                const ulonglong2 w = *reinterpret_cast<const ulonglong2*>(&sW1[k * HID + hg]);
                fma2(acc[0], xb, w.x);
                fma2(acc[1], xb, w.y);
            }
            float* hrow = &sH[r * HPAD + hg];
            float l0, h0, l1, h1;
            unpack2(acc[0], l0, h0);
            unpack2(acc[1], l1, h1);
            *reinterpret_cast<float2*>(hrow)     = make_float2(fmaxf(l0, 0.f), fmaxf(h0, 0.f));
            *reinterpret_cast<float2*>(hrow + 2) = make_float2(fmaxf(l1, 0.f), fmaxf(h1, 0.f));
        }
        __syncthreads();   // sH ready; sX free for prefetch

        // ---- prefetch X of next tile (hidden under GEMM) ----
        if (tile + GRID < NTILES) {
            int nrow0 = (tile + GRID) * ROWS;
            if (tid < 512) {
                int r = tid >> 3, c4 = tid & 7;
                cp16(sXaddr + (r * XPAD + c4 * 4) * 4,
                     &s[(size_t)(nrow0 + r) * SDIM + c4 * 4]);
            } else if (tid < 640) {
                int t2 = tid - 512, r2 = t2 >> 1, d4 = t2 & 1;
                cp16(sXaddr + (r2 * XPAD + SDIM + d4 * 4) * 4,
                     &a[(size_t)(nrow0 + r2) * ADIM + d4 * 4]);
            }
            cp_commit();
        }

        // ---- Phase 2: tri = H @ W2^T + b2 (thread tile 4r x 9c) ----
        u64   acc2[4][4];   // paired cols: {4cg..+3, 16+4cg..+3}
        float accs[4];      // scalar tail col 32+cg
        {
            u64 b0 = *reinterpret_cast<const u64*>(&sB2[wcol + 4 * cg]);
            u64 b1p = *reinterpret_cast<const u64*>(&sB2[wcol + 4 * cg + 2]);
            u64 b2p = *reinterpret_cast<const u64*>(&sB2[wcol + 16 + 4 * cg]);
            u64 b3p = *reinterpret_cast<const u64*>(&sB2[wcol + 16 + 4 * cg + 2]);
            float bt = sB2[wcol + 32 + cg];
#pragma unroll
            for (int m = 0; m < 4; ++m) {
                acc2[m][0] = b0; acc2[m][1] = b1p;
                acc2[m][2] = b2p; acc2[m][3] = b3p;
                accs[m] = bt;
            }
        }

        const float* hbase = &sH[(rb * 32 + rg) * HPAD];
#pragma unroll 2
        for (int k = 0; k < HID; k += 2) {
            // h for 2 k-steps, 4 rows (float2, conflict-free banked)
            float2 hp[4];
#pragma unroll
            for (int m = 0; m < 4; ++m)
                hp[m] = *reinterpret_cast<const float2*>(&hbase[m * 8 * HPAD + k]);
#pragma unroll
            for (int kk = 0; kk < 2; ++kk) {
                const float* wr = &sW2[(k + kk) * NPAD + wcol];
                const ulonglong2 wq0 = *reinterpret_cast<const ulonglong2*>(wr + 4 * cg);
                const ulonglong2 wq1 = *reinterpret_cast<const ulonglong2*>(wr + 16 + 4 * cg);
                const float wt = wr[32 + cg];
#pragma unroll
                for (int m = 0; m < 4; ++m) {
                    const float hv = kk ? hp[m].y : hp[m].x;
                    const u64 hb = pack2(hv, hv);
                    fma2(acc2[m][0], hb, wq0.x);
                    fma2(acc2[m][1], hb, wq0.y);
                    fma2(acc2[m][2], hb, wq1.x);
                    fma2(acc2[m][3], hb, wq1.y);
                    accs[m] = fmaf(hv, wt, accs[m]);
                }
            }
        }

        // ---- Phase 3: 4 chunked epilogue phases of 16 rows each ----
        // Thread rows: rb*32 + rg + 8m. Phase p covers [16p, 16p+16):
        // writers: rb == p>>1, m = 2*(p&1) + mm; chunk row = rg + 8*mm.
#pragma unroll
        for (int p = 0; p < 4; ++p) {
            if (rb == (p >> 1)) {
                const int mb = (p & 1) * 2;
#pragma unroll
                for (int mm = 0; mm < 2; ++mm) {
                    const int m = mb + mm;
                    float* trow = &sTri[(rg + 8 * mm) * TPAD + wcol];
                    *reinterpret_cast<u64*>(trow + 4 * cg)          = acc2[m][0];
                    *reinterpret_cast<u64*>(trow + 4 * cg + 2)      = acc2[m][1];
                    *reinterpret_cast<u64*>(trow + 16 + 4 * cg)     = acc2[m][2];
                    *reinterpret_cast<u64*>(trow + 16 + 4 * cg + 2) = acc2[m][3];
                    trow[32 + cg] = accs[m];
                }
            }
            __syncthreads();

            // coalesced scatter of 16 rows (4 quads per thread)
            float4* out4 = reinterpret_cast<float4*>(out + (size_t)(row0 + p * 16) * 1024);
#pragma unroll
            for (int it = 0; it < 4; ++it) {
                const int idx = tid + it * NT;
                const int r  = idx >> 8;
                const int o4 = idx & 255;
                const int4 tt = tbl4[o4];
                const float* tr = &sTri[r * TPAD];
                float v0 = tr[tt.x & 0xffff];
                float v1 = tr[tt.y & 0xffff];
                float v2 = tr[tt.z & 0xffff];
                float v3 = tr[tt.w & 0xffff];
                if (tt.x >> 16) v0 = __expf(v0);
                if (tt.y >> 16) v1 = __expf(v1);
                if (tt.z >> 16) v2 = __expf(v2);
                if (tt.w >> 16) v3 = __expf(v3);
                out4[idx] = make_float4(v0, v1, v2, v3);
            }
            if (p == 3) cp_wait0();   // X(t+1) landed before the barrier below
            __syncthreads();
        }
    }
}

extern "C" void kernel_launch(void* const* d_in, const int* in_sizes, int n_in,
                              void* d_out, int out_size) {
    (void)in_sizes; (void)n_in; (void)out_size;
    const float* s  = (const float*)d_in[0];
    const float* a  = (const float*)d_in[1];
    const float* W1 = (const float*)d_in[2];
    const float* b1 = (const float*)d_in[3];
    const float* W2 = (const float*)d_in[4];
    const float* b2 = (const float*)d_in[5];
    float* out = (float*)d_out;

    const size_t smem_bytes = SM_FLOATS * sizeof(float);  // 229504
    cudaFuncSetAttribute(sigma_persist_kernel,
                         cudaFuncAttributeMaxDynamicSharedMemorySize,
                         (int)smem_bytes);
    sigma_persist_kernel<<<GRID, NT, smem_bytes>>>(s, a, W1, b1, W2, b2, out);
}